// round 9
// baseline (speedup 1.0000x reference)
#include <cuda_runtime.h>
#include <cstdint>

// Hierarchical polarization:
//   P_0 = pairwise means of Z;  P_{L+1}[G] = mean over pair of (P_L + At_L)
//   out = Z + sum_L At_L[group(s,L)]
// setup_pack:   pre-pack weights for f32x2 inner loops.
// stage_kernel: 16-row tiles, 28KB smem/CTA -> 4 CTAs/SM with L1D=116KB so the
//               64KB per-level weight set stays L1-resident.
//               S1: L0..4 (4096 CTAs from Z), S2: L5..9 (128 CTAs), S3: L10..13 (4 CTAs).
// final_kernel: out = Z + gather over At pyramid.

typedef unsigned long long u64;

__device__ float  g_At[33554432];     // At pyramid, 14 levels, 128 MiB
__device__ float  g_uA[4096 * 256];   // updated level-4 rows
__device__ float  g_uB[128 * 256];    // updated level-9 rows
__device__ float4 g_W1p[10 * 2048];   // [t][dd=0..63][lane]: (w1[4dd..4dd+3][lane])
__device__ u64    g_W2p[10 * 4096];   // [t][j][kk*32+l]: (w2[j][l+64kk], w2[j][l+64kk+32])
__device__ u64    g_b2p[10 * 128];    // [t][kk*32+l]:    (b2[l+64kk],    b2[l+64kk+32])

__device__ __forceinline__ u64 pack2(float lo, float hi) {
    u64 r; asm("mov.b64 %0, {%1, %2};" : "=l"(r) : "f"(lo), "f"(hi)); return r;
}
__device__ __forceinline__ void unpack2(u64 v, float& lo, float& hi) {
    asm("mov.b64 {%0, %1}, %2;" : "=f"(lo), "=f"(hi) : "l"(v));
}
__device__ __forceinline__ u64 ffma2(u64 a, u64 b, u64 c) {
    u64 d; asm("fma.rn.f32x2 %0, %1, %2, %3;" : "=l"(d) : "l"(a), "l"(b), "l"(c)); return d;
}
__device__ __forceinline__ u64 fadd2(u64 a, u64 b) {
    u64 d; asm("add.rn.f32x2 %0, %1, %2;" : "=l"(d) : "l"(a), "l"(b)); return d;
}
__device__ __forceinline__ float4 ldcs4(const float4* p) {
    float4 v;
    asm volatile("ld.global.cs.v4.f32 {%0,%1,%2,%3}, [%4];"
                 : "=f"(v.x), "=f"(v.y), "=f"(v.z), "=f"(v.w) : "l"(p));
    return v;
}
__device__ __forceinline__ float gelu_tanh(float x) {
    // jax.nn.gelu approximate=True; tanh(u) = 1 - 2/(exp(2u)+1)
    float u = 0.7978845608028654f * (x + 0.044715f * x * x * x);
    float e = __expf(2.0f * u);
    float t = 1.0f - __fdividef(2.0f, e + 1.0f);
    return 0.5f * x * (1.0f + t);
}
__device__ __forceinline__ long long offF(int l) {   // float offset of level l in At
    return (131072LL - (131072LL >> l)) * 256LL;
}

// ---------------------------------------------------------------------------
__global__ void setup_pack(const float* __restrict__ W1, const float* __restrict__ W2,
                           const float* __restrict__ b2)
{
    int t = blockIdx.x, tid = threadIdx.x;
    const float* w1 = W1 + t * 8192;
    for (int i = tid; i < 2048; i += 256) {
        int dd = i >> 5, l = i & 31;
        g_W1p[t * 2048 + i] = make_float4(
            w1[(4 * dd + 0) * 32 + l], w1[(4 * dd + 1) * 32 + l],
            w1[(4 * dd + 2) * 32 + l], w1[(4 * dd + 3) * 32 + l]);
    }
    const float* w2 = W2 + t * 8192;
    for (int i = tid; i < 4096; i += 256) {
        int j = i >> 7, r = i & 127, kk = r >> 5, l = r & 31;
        g_W2p[t * 4096 + i] = pack2(w2[j * 256 + l + 64 * kk],
                                    w2[j * 256 + l + 64 * kk + 32]);
    }
    if (tid < 128) {
        int kk = tid >> 5, l = tid & 31;
        g_b2p[t * 128 + tid] = pack2(b2[t * 256 + l + 64 * kk],
                                     b2[t * 256 + l + 64 * kk + 32]);
    }
}

// ---------------------------------------------------------------------------
// Phase 1: H rows rb..rb+CP-1 = gelu(X @ W1 + b1). f32x2 over adjacent d's.
// X loads are LDS.128 broadcasts; W loads are coalesced LDG.128 (L1-resident).
// ---------------------------------------------------------------------------
template<int CP>
__device__ __forceinline__ void phase1_chunk(
    const float* __restrict__ Xc, u64* __restrict__ Hd, int rb,
    const float4* __restrict__ W1p, const float* __restrict__ b1v, int lane)
{
    u64 aA[CP], aB[CP];
    #pragma unroll
    for (int c = 0; c < CP; c++) { aA[c] = 0ULL; aB[c] = 0ULL; }
    const float4* X4 = (const float4*)Xc;
    #pragma unroll 8
    for (int dd = 0; dd < 64; dd++) {
        union { float4 f; u64 u[2]; } w; w.f = W1p[dd * 32 + lane];
        #pragma unroll
        for (int c = 0; c < CP; c++) {
            union { float4 f; u64 u[2]; } x; x.f = X4[(rb + c) * 64 + dd];
            aA[c] = ffma2(x.u[0], w.u[0], aA[c]);
            aB[c] = ffma2(x.u[1], w.u[1], aB[c]);
        }
    }
    float bb = b1v[lane];
    #pragma unroll
    for (int c = 0; c < CP; c++) {
        float lo, hi; unpack2(fadd2(aA[c], aB[c]), lo, hi);
        float h = gelu_tanh(lo + hi + bb);
        Hd[(rb + c) * 32 + lane] = pack2(h, h);
    }
}

// ---------------------------------------------------------------------------
// Phase 3 for a row pair: At = H @ W2 + b2 (stored), Xn[pp] = pair mean of x+At.
// f32x2 packs output dims (d, d+32); H reads are LDS.64 broadcasts.
// ---------------------------------------------------------------------------
__device__ __forceinline__ void phase3_pair(
    const float* __restrict__ Xc, float* __restrict__ Xn, const u64* __restrict__ Hd,
    int pp, float* __restrict__ AtB,
    const u64* __restrict__ W2p, const u64* __restrict__ b2p, int lane)
{
    const int r0 = 2 * pp, r1 = r0 + 1;
    u64 a0[4], a1[4];
    #pragma unroll
    for (int kk = 0; kk < 4; kk++) { u64 b = b2p[kk * 32 + lane]; a0[kk] = b; a1[kk] = b; }
    const u64* H0 = Hd + r0 * 32;
    const u64* H1 = Hd + r1 * 32;
    #pragma unroll 4
    for (int j = 0; j < 32; j++) {
        u64 h0 = H0[j], h1 = H1[j];
        const u64* wr = W2p + j * 128 + lane;
        #pragma unroll
        for (int kk = 0; kk < 4; kk++) {
            u64 w = wr[kk * 32];
            a0[kk] = ffma2(h0, w, a0[kk]);
            a1[kk] = ffma2(h1, w, a1[kk]);
        }
    }
    #pragma unroll
    for (int kk = 0; kk < 4; kk++) {
        int da = lane + 64 * kk, db = da + 32;
        float p0a, p0b, p1a, p1b;
        unpack2(a0[kk], p0a, p0b); unpack2(a1[kk], p1a, p1b);
        AtB[r0 * 256 + da] = p0a; AtB[r0 * 256 + db] = p0b;
        AtB[r1 * 256 + da] = p1a; AtB[r1 * 256 + db] = p1b;
        Xn[pp * 256 + da] = 0.5f * ((Xc[r0 * 256 + da] + p0a) + (Xc[r1 * 256 + da] + p1a));
        Xn[pp * 256 + db] = 0.5f * ((Xc[r0 * 256 + db] + p0b) + (Xc[r1 * 256 + db] + p1b));
    }
}

// Last level of a stage (nr == 1): At + optional updated row (x + At) to global.
__device__ __forceinline__ void final_row(
    const float* __restrict__ Xc, const u64* __restrict__ Hd,
    float* __restrict__ AtB, float* __restrict__ uOut,
    const u64* __restrict__ W2p, const u64* __restrict__ b2p, int lane)
{
    u64 a[4];
    #pragma unroll
    for (int kk = 0; kk < 4; kk++) a[kk] = b2p[kk * 32 + lane];
    #pragma unroll 4
    for (int j = 0; j < 32; j++) {
        u64 h = Hd[j];
        const u64* wr = W2p + j * 128 + lane;
        #pragma unroll
        for (int kk = 0; kk < 4; kk++) a[kk] = ffma2(h, wr[kk * 32], a[kk]);
    }
    #pragma unroll
    for (int kk = 0; kk < 4; kk++) {
        int da = lane + 64 * kk, db = da + 32;
        float pa, pb; unpack2(a[kk], pa, pb);
        AtB[da] = pa; AtB[db] = pb;
        if (uOut) { uOut[da] = Xc[da] + pa; uOut[db] = Xc[db] + pb; }
    }
}

// ---------------------------------------------------------------------------
// Generic stage: CTA takes 32 input rows, entry X = pair means (16 rows), then
// nLev levels of (MLP -> At -> pair means). src: 0=Z, 1=g_uA, 2=g_uB.
// Smem: Xa 16KB | Xb 8KB | Hd 4KB = 28KB -> 4 CTAs/SM, L1D = 116KB.
// ---------------------------------------------------------------------------
__global__ void __launch_bounds__(256, 4) stage_kernel(
    const float4* __restrict__ Z4, int src, int l0, int nLev,
    const float* __restrict__ b1all)
{
    extern __shared__ float sm[];
    float* Xa = sm;                    // 16 rows
    float* Xb = sm + 4096;             // 8 rows
    u64*   Hd = (u64*)(sm + 6144);     // 16 rows x 32 u64

    const int bi   = blockIdx.x;
    const int tid  = threadIdx.x;
    const int lane = tid & 31;
    const int wp   = tid >> 5;

    const float4* in4 =
        (src == 0) ? (Z4 + (long long)bi * 2048)
                   : ((src == 1) ? ((const float4*)g_uA + (long long)bi * 2048)
                                 : ((const float4*)g_uB + (long long)bi * 2048));
    float* uOut = (src == 0) ? (g_uA + bi * 256)
                             : ((src == 1) ? (g_uB + bi * 256) : nullptr);

    // ---- entry: X = pair means of 32 input rows (streaming loads, keep L1) ----
    for (int i = tid; i < 1024; i += 256) {
        int r = i >> 6, c = i & 63;
        float4 a = ldcs4(in4 + (2 * r) * 64 + c);
        float4 b = ldcs4(in4 + (2 * r + 1) * 64 + c);
        ((float4*)Xa)[i] = make_float4(0.5f * (a.x + b.x), 0.5f * (a.y + b.y),
                                       0.5f * (a.z + b.z), 0.5f * (a.w + b.w));
    }
    __syncthreads();

    float* Xc = Xa; float* Xn = Xb;
    int nr = 16;
    for (int i = 0; i < nLev; i++) {
        int l  = l0 + i;
        int tt = (l < 10) ? l : 9;
        const float4* W1p = g_W1p + tt * 2048;
        const float*  b1v = b1all + tt * 32;
        const u64*    W2p = g_W2p + tt * 4096;
        const u64*    b2p = g_b2p + tt * 128;
        float* AtB = g_At + offF(l) + (long long)bi * nr * 256;

        // phase 1 -> Hd (all 8 warps busy at nr=16 via CP=2)
        if (nr == 16) {
            phase1_chunk<2>(Xc, Hd, 2 * wp, W1p, b1v, lane);
        } else {
            if (wp < nr) phase1_chunk<1>(Xc, Hd, wp, W1p, b1v, lane);
        }
        __syncthreads();

        if (nr == 1) {
            if (wp == 0) final_row(Xc, Hd, AtB, uOut, W2p, b2p, lane);
            __syncthreads();
        } else {
            int np = nr >> 1;
            for (int pp = wp; pp < np; pp += 8)
                phase3_pair(Xc, Xn, Hd, pp, AtB, W2p, b2p, lane);
            __syncthreads();
        }
        float* t2 = Xc; Xc = Xn; Xn = t2;
        nr >>= 1;
    }
}

// ---------------------------------------------------------------------------
// out = Z + sum over 14 levels of At[level][b, s>>(L+1), d]
// ---------------------------------------------------------------------------
__global__ void __launch_bounds__(256) final_kernel(
    const float4* __restrict__ Z4, float4* __restrict__ out4)
{
    int i   = blockIdx.x * 256 + threadIdx.x;
    int d4  = i & 63;
    int row = i >> 6;
    int b   = row >> 14;
    int s   = row & 16383;

    const float4* At4 = (const float4*)g_At;
    float4 acc = Z4[i];
    long long off4 = 0;
    int ng = 8192;
    #pragma unroll
    for (int L = 0; L < 14; L++) {
        int g = s >> (L + 1);
        float4 a = At4[off4 + (long long)(b * ng + g) * 64 + d4];
        acc.x += a.x; acc.y += a.y; acc.z += a.z; acc.w += a.w;
        off4 += 512LL * ng;
        ng >>= 1;
    }
    out4[i] = acc;
}

extern "C" void kernel_launch(void* const* d_in, const int* in_sizes, int n_in,
                              void* d_out, int out_size)
{
    const float* Z  = (const float*)d_in[0];
    const float* W1 = (const float*)d_in[1];
    const float* b1 = (const float*)d_in[2];
    const float* W2 = (const float*)d_in[3];
    const float* b2 = (const float*)d_in[4];

    const int SMEM = 28672;   // 16KB Xa + 8KB Xb + 4KB Hd
    cudaFuncSetAttribute(stage_kernel, cudaFuncAttributeMaxDynamicSharedMemorySize, SMEM);

    setup_pack<<<10, 256>>>(W1, W2, b2);
    stage_kernel<<<4096, 256, SMEM>>>((const float4*)Z, 0, 0, 5, b1);    // L0..4
    stage_kernel<<<128,  256, SMEM>>>((const float4*)Z, 1, 5, 5, b1);    // L5..9
    stage_kernel<<<4,    256, SMEM>>>((const float4*)Z, 2, 10, 4, b1);   // L10..13
    final_kernel<<<32768, 256>>>((const float4*)Z, (float4*)d_out);
}

// round 16
// speedup vs baseline: 1.2829x; 1.2829x over previous
#include <cuda_runtime.h>
#include <cuda_bf16.h>
#include <cstdint>

// Hierarchical polarization on warp-level bf16 tensor cores (mma.sync, sm_80+
// feature set -- no 'a'-suffix target needed).
//   P_0 = pairwise means of Z;  P_{L+1}[G] = mean over pair of (P_L + At_L)
//   out = Z + sum_L At_L[group(s,L)]
// Per level: CTA = 64 P-rows.
//   GEMM1 D1 = X @ W1^T (K=256), 3 split-bf16 passes, f32 accum
//   H = gelu(D1 + b1), re-split to bf16 hi/lo in smem
//   GEMM2 D2 = H @ W2^T (K=32), 3 passes; At = D2 + b2
//   epilogue: store At; next-level P = pair means of (X + At) via shfl.
// NOTE: for L>0 the input rows are ALREADY the level's X rows (the previous
// level's epilogue stored the pair means) -- only L0 pair-means from Z.

typedef unsigned int u32;

__device__ float g_At[33554432];            // At pyramid, 14 levels, 128 MiB
__device__ float g_UA[8388608];             // P out, even levels
__device__ float g_UB[4194304];             // P out, odd levels
__device__ __nv_bfloat16 g_W1h[10 * 8448];  // [t][h=32][d pad264]  (B for GEMM1)
__device__ __nv_bfloat16 g_W1l[10 * 8448];
__device__ __nv_bfloat16 g_W2h[10 * 10240]; // [t][d=256][h pad40]  (B for GEMM2)
__device__ __nv_bfloat16 g_W2l[10 * 10240];
__device__ float g_b1[320];
__device__ float g_b2[2560];

__device__ __forceinline__ float gelu_tanh(float x) {
    // jax.nn.gelu approximate=True; tanh(u) = 1 - 2/(exp(2u)+1)
    float u = 0.7978845608028654f * (x + 0.044715f * x * x * x);
    float e = __expf(2.0f * u);
    float t = 1.0f - __fdividef(2.0f, e + 1.0f);
    return 0.5f * x * (1.0f + t);
}
__device__ __forceinline__ long long offF(int l) {
    return (131072LL - (131072LL >> l)) * 256LL;
}
__device__ __forceinline__ void split2(float a, float b, u32& hi, u32& lo) {
    __nv_bfloat16 ha = __float2bfloat16(a), hb = __float2bfloat16(b);
    __nv_bfloat16 la = __float2bfloat16(a - __bfloat162float(ha));
    __nv_bfloat16 lb = __float2bfloat16(b - __bfloat162float(hb));
    hi = (u32)*(unsigned short*)&ha | ((u32)*(unsigned short*)&hb << 16);
    lo = (u32)*(unsigned short*)&la | ((u32)*(unsigned short*)&lb << 16);
}
__device__ __forceinline__ float2 unbf2(u32 v) {
    __nv_bfloat162 t = *(__nv_bfloat162*)&v;
    return make_float2(__bfloat162float(t.x), __bfloat162float(t.y));
}
// D += A(16x16 row) * B(16x8 col), bf16 -> f32
__device__ __forceinline__ void mma16816(float* d, const u32* a, const u32* b) {
    asm volatile("mma.sync.aligned.m16n8k16.row.col.f32.bf16.bf16.f32 "
                 "{%0,%1,%2,%3}, {%4,%5,%6,%7}, {%8,%9}, {%0,%1,%2,%3};"
                 : "+f"(d[0]), "+f"(d[1]), "+f"(d[2]), "+f"(d[3])
                 : "r"(a[0]), "r"(a[1]), "r"(a[2]), "r"(a[3]), "r"(b[0]), "r"(b[1]));
}

// ---------------------------------------------------------------------------
// Pre-split + transpose weights into padded row-major B images.
//   GEMM1 B[k=d][n=h] col-major == W1T[h][d] row-major (stride 264)
//   GEMM2 B[k=h][n=d] col-major == W2T[d][h] row-major (stride 40)
// ---------------------------------------------------------------------------
__global__ void setup_weights(const float* __restrict__ W1, const float* __restrict__ W2,
                              const float* __restrict__ b1, const float* __restrict__ b2)
{
    int t = blockIdx.x, tid = threadIdx.x;
    for (int e = tid; e < 8448; e += 256) {
        int h = e / 264, d = e % 264;
        float v = (d < 256) ? W1[t * 8192 + d * 32 + h] : 0.f;
        __nv_bfloat16 hi = __float2bfloat16(v);
        __nv_bfloat16 lo = __float2bfloat16(v - __bfloat162float(hi));
        g_W1h[t * 8448 + e] = hi;
        g_W1l[t * 8448 + e] = lo;
    }
    for (int e = tid; e < 10240; e += 256) {
        int d = e / 40, h = e % 40;
        float v = (h < 32) ? W2[t * 8192 + h * 256 + d] : 0.f;
        __nv_bfloat16 hi = __float2bfloat16(v);
        __nv_bfloat16 lo = __float2bfloat16(v - __bfloat162float(hi));
        g_W2h[t * 10240 + e] = hi;
        g_W2l[t * 10240 + e] = lo;
    }
    if (tid < 32)  g_b1[t * 32 + tid] = b1[t * 32 + tid];
    if (tid < 256) g_b2[t * 256 + tid] = b2[t * 256 + tid];
}

// ---------------------------------------------------------------------------
// Smem layout (bytes). Strides chosen for conflict-free MMA fragment LDS:
//   X stride 264 bf16 (528B = 132 u32, 132%32=4) ; H/W2 stride 40 (80B=20 u32).
// ---------------------------------------------------------------------------
#define XS 264
#define HS 40
#define SM_XHI 0
#define SM_XLO 33792
#define SM_HHI 67584
#define SM_HLO 72704
#define SM_W1H 77824
#define SM_W1L 94720
#define SM_W2H 111616
#define SM_W2L 132096
#define SMEM_TOTAL 152576

__global__ void __launch_bounds__(256, 1) mma_level_kernel(
    const float4* __restrict__ Z4, int L, int tt, int nr)
{
    extern __shared__ char sm[];
    __nv_bfloat16* Xh = (__nv_bfloat16*)(sm + SM_XHI);
    __nv_bfloat16* Xl = (__nv_bfloat16*)(sm + SM_XLO);
    __nv_bfloat16* Hh = (__nv_bfloat16*)(sm + SM_HHI);
    __nv_bfloat16* Hl = (__nv_bfloat16*)(sm + SM_HLO);
    __nv_bfloat16* W1hS = (__nv_bfloat16*)(sm + SM_W1H);
    __nv_bfloat16* W1lS = (__nv_bfloat16*)(sm + SM_W1L);
    __nv_bfloat16* W2hS = (__nv_bfloat16*)(sm + SM_W2H);
    __nv_bfloat16* W2lS = (__nv_bfloat16*)(sm + SM_W2L);

    const int tid  = threadIdx.x;
    const int lane = tid & 31;
    const int w    = tid >> 5;
    const long long rbase = (long long)blockIdx.x * 64;

    const float4* Pin = (L == 0) ? Z4
                      : ((L & 1) ? (const float4*)g_UA : (const float4*)g_UB);
    float* Pout  = (L & 1) ? g_UB : g_UA;
    float* AtOut = g_At + offF(L);

    // ---- copy weight images (plain u32 copies; images pre-padded) ----
    {
        u32* d1h = (u32*)W1hS; const u32* s1h = (const u32*)(g_W1h + tt * 8448);
        u32* d1l = (u32*)W1lS; const u32* s1l = (const u32*)(g_W1l + tt * 8448);
        for (int i = tid; i < 4224; i += 256) { d1h[i] = s1h[i]; d1l[i] = s1l[i]; }
        u32* d2h = (u32*)W2hS; const u32* s2h = (const u32*)(g_W2h + tt * 10240);
        u32* d2l = (u32*)W2lS; const u32* s2l = (const u32*)(g_W2l + tt * 10240);
        for (int i = tid; i < 5120; i += 256) { d2h[i] = s2h[i]; d2l[i] = s2l[i]; }
    }
    // ---- fill X: L0 = pair means of Z rows; L>0 = direct copy of P rows ----
    {
        int r  = tid >> 2;               // 0..63
        int cb = (tid & 3) * 16;         // float4 index base
        bool v = r < nr;
        if (L == 0) {
            const float4* p0 = Pin + (2 * (rbase + r)) * 64;
            const float4* p1 = p0 + 64;
            #pragma unroll 4
            for (int m = 0; m < 16; m++) {
                int c4 = cb + m;
                float4 a = v ? p0[c4] : make_float4(0.f, 0.f, 0.f, 0.f);
                float4 b = v ? p1[c4] : make_float4(0.f, 0.f, 0.f, 0.f);
                float x0 = 0.5f * (a.x + b.x), x1 = 0.5f * (a.y + b.y);
                float x2 = 0.5f * (a.z + b.z), x3 = 0.5f * (a.w + b.w);
                u32 h01, l01, h23, l23;
                split2(x0, x1, h01, l01);
                split2(x2, x3, h23, l23);
                int c = 4 * c4;
                *(u32*)&Xh[r * XS + c]     = h01;
                *(u32*)&Xh[r * XS + c + 2] = h23;
                *(u32*)&Xl[r * XS + c]     = l01;
                *(u32*)&Xl[r * XS + c + 2] = l23;
            }
        } else {
            const float4* p0 = Pin + (rbase + r) * 64;
            #pragma unroll 4
            for (int m = 0; m < 16; m++) {
                int c4 = cb + m;
                float4 a = v ? p0[c4] : make_float4(0.f, 0.f, 0.f, 0.f);
                u32 h01, l01, h23, l23;
                split2(a.x, a.y, h01, l01);
                split2(a.z, a.w, h23, l23);
                int c = 4 * c4;
                *(u32*)&Xh[r * XS + c]     = h01;
                *(u32*)&Xh[r * XS + c + 2] = h23;
                *(u32*)&Xl[r * XS + c]     = l01;
                *(u32*)&Xl[r * XS + c + 2] = l23;
            }
        }
    }
    __syncthreads();

    const int r  = lane >> 2;    // 0..7
    const int cq = lane & 3;     // 0..3

    // ---- GEMM1: warp w -> rows R0..R0+15, cols C1..C1+15 of D1 ----
    const int R0 = (w & 3) * 16;
    const int C1 = (w >> 2) * 16;
    {
        float acc[2][4] = {};
        #pragma unroll 4
        for (int k = 0; k < 16; k++) {
            int kb = k * 16;
            const __nv_bfloat16* xr = Xh + (R0 + r) * XS + kb + 2 * cq;
            const __nv_bfloat16* xs = Xl + (R0 + r) * XS + kb + 2 * cq;
            u32 ah[4] = { *(u32*)xr, *(u32*)(xr + 8 * XS), *(u32*)(xr + 8), *(u32*)(xr + 8 * XS + 8) };
            u32 al[4] = { *(u32*)xs, *(u32*)(xs + 8 * XS), *(u32*)(xs + 8), *(u32*)(xs + 8 * XS + 8) };
            #pragma unroll
            for (int j = 0; j < 2; j++) {
                const __nv_bfloat16* wr = W1hS + (C1 + 8 * j + r) * XS + kb + 2 * cq;
                const __nv_bfloat16* ws = W1lS + (C1 + 8 * j + r) * XS + kb + 2 * cq;
                u32 bh[2] = { *(u32*)wr, *(u32*)(wr + 8) };
                u32 bl[2] = { *(u32*)ws, *(u32*)(ws + 8) };
                mma16816(acc[j], ah, bh);
                mma16816(acc[j], al, bh);
                mma16816(acc[j], ah, bl);
            }
        }
        // H = gelu(D1 + b1), split, store
        const float* b1v = g_b1 + tt * 32;
        #pragma unroll
        for (int j = 0; j < 2; j++) {
            int c = C1 + 8 * j + 2 * cq;
            float h0 = gelu_tanh(acc[j][0] + b1v[c]);
            float h1 = gelu_tanh(acc[j][1] + b1v[c + 1]);
            float h2 = gelu_tanh(acc[j][2] + b1v[c]);
            float h3 = gelu_tanh(acc[j][3] + b1v[c + 1]);
            u32 hi, lo;
            split2(h0, h1, hi, lo);
            *(u32*)&Hh[(R0 + r) * HS + c] = hi;
            *(u32*)&Hl[(R0 + r) * HS + c] = lo;
            split2(h2, h3, hi, lo);
            *(u32*)&Hh[(R0 + r + 8) * HS + c] = hi;
            *(u32*)&Hl[(R0 + r + 8) * HS + c] = lo;
        }
    }
    __syncthreads();

    // ---- GEMM2: warp w -> rows R0..R0+15, cols Cb..Cb+127, 2 chunks of 64 ----
    const int Cb = (w >> 2) * 128;
    const float* b2v = g_b2 + tt * 256;
    for (int ch = 0; ch < 2; ch++) {
        int C2 = Cb + 64 * ch;
        float acc2[8][4] = {};
        #pragma unroll
        for (int k = 0; k < 2; k++) {
            int kb = 16 * k;
            const __nv_bfloat16* hr = Hh + (R0 + r) * HS + kb + 2 * cq;
            const __nv_bfloat16* hs = Hl + (R0 + r) * HS + kb + 2 * cq;
            u32 ah[4] = { *(u32*)hr, *(u32*)(hr + 8 * HS), *(u32*)(hr + 8), *(u32*)(hr + 8 * HS + 8) };
            u32 al[4] = { *(u32*)hs, *(u32*)(hs + 8 * HS), *(u32*)(hs + 8), *(u32*)(hs + 8 * HS + 8) };
            #pragma unroll
            for (int j = 0; j < 8; j++) {
                const __nv_bfloat16* wr = W2hS + (C2 + 8 * j + r) * HS + kb + 2 * cq;
                const __nv_bfloat16* ws = W2lS + (C2 + 8 * j + r) * HS + kb + 2 * cq;
                u32 bh[2] = { *(u32*)wr, *(u32*)(wr + 8) };
                u32 bl[2] = { *(u32*)ws, *(u32*)(ws + 8) };
                mma16816(acc2[j], ah, bh);
                mma16816(acc2[j], al, bh);
                mma16816(acc2[j], ah, bl);
            }
        }
        // ---- epilogue: At stores + next-level P (pair means via shfl) ----
        #pragma unroll
        for (int j = 0; j < 8; j++) {
            int c = C2 + 8 * j + 2 * cq;
            float b20 = b2v[c], b21 = b2v[c + 1];
            float at00 = acc2[j][0] + b20, at01 = acc2[j][1] + b21;
            float at10 = acc2[j][2] + b20, at11 = acc2[j][3] + b21;
            int row0 = R0 + r, row1 = R0 + r + 8;
            float2 xh0 = unbf2(*(u32*)&Xh[row0 * XS + c]);
            float2 xl0 = unbf2(*(u32*)&Xl[row0 * XS + c]);
            float2 xh1 = unbf2(*(u32*)&Xh[row1 * XS + c]);
            float2 xl1 = unbf2(*(u32*)&Xl[row1 * XS + c]);
            float u00 = xh0.x + xl0.x + at00, u01 = xh0.y + xl0.y + at01;
            float u10 = xh1.x + xl1.x + at10, u11 = xh1.y + xl1.y + at11;
            float p00 = __shfl_xor_sync(0xFFFFFFFFu, u00, 4);
            float p01 = __shfl_xor_sync(0xFFFFFFFFu, u01, 4);
            float p10 = __shfl_xor_sync(0xFFFFFFFFu, u10, 4);
            float p11 = __shfl_xor_sync(0xFFFFFFFFu, u11, 4);
            if (row0 < nr) {
                *(float2*)&AtOut[(rbase + row0) * 256 + c] = make_float2(at00, at01);
                if (row1 < nr)
                    *(float2*)&AtOut[(rbase + row1) * 256 + c] = make_float2(at10, at11);
                if (!(r & 1)) {
                    *(float2*)&Pout[((rbase + row0) >> 1) * 256 + c] =
                        make_float2(0.5f * (u00 + p00), 0.5f * (u01 + p01));
                    if (row1 < nr)
                        *(float2*)&Pout[((rbase + row1) >> 1) * 256 + c] =
                            make_float2(0.5f * (u10 + p10), 0.5f * (u11 + p11));
                }
            }
        }
    }
}

// ---------------------------------------------------------------------------
// out = Z + sum over 14 levels of At[level][b, s>>(L+1), d]
// ---------------------------------------------------------------------------
__global__ void __launch_bounds__(256) final_kernel(
    const float4* __restrict__ Z4, float4* __restrict__ out4)
{
    int i   = blockIdx.x * 256 + threadIdx.x;
    int d4  = i & 63;
    int row = i >> 6;
    int b   = row >> 14;
    int s   = row & 16383;

    const float4* At4 = (const float4*)g_At;
    float4 acc = Z4[i];
    long long off4 = 0;
    int ng = 8192;
    #pragma unroll
    for (int L = 0; L < 14; L++) {
        int g = s >> (L + 1);
        float4 a = At4[off4 + (long long)(b * ng + g) * 64 + d4];
        acc.x += a.x; acc.y += a.y; acc.z += a.z; acc.w += a.w;
        off4 += 512LL * ng;
        ng >>= 1;
    }
    out4[i] = acc;
}

extern "C" void kernel_launch(void* const* d_in, const int* in_sizes, int n_in,
                              void* d_out, int out_size)
{
    const float* Z  = (const float*)d_in[0];
    const float* W1 = (const float*)d_in[1];
    const float* b1 = (const float*)d_in[2];
    const float* W2 = (const float*)d_in[3];
    const float* b2 = (const float*)d_in[4];

    cudaFuncSetAttribute(mma_level_kernel,
                         cudaFuncAttributeMaxDynamicSharedMemorySize, SMEM_TOTAL);

    setup_weights<<<10, 256>>>(W1, W2, b1, b2);

    for (int L = 0; L < 14; L++) {
        int rowsP = 65536 >> L;
        int grid  = (rowsP >= 64) ? (rowsP / 64) : 1;
        int nr    = (rowsP >= 64) ? 64 : rowsP;
        int tt    = (L < 10) ? L : 9;
        mma_level_kernel<<<grid, 256, SMEM_TOTAL>>>((const float4*)Z, L, tt, nr);
    }
    final_kernel<<<32768, 256>>>((const float4*)Z, (float4*)d_out);
}

// round 17
// speedup vs baseline: 1.7855x; 1.3918x over previous
#include <cuda_runtime.h>
#include <cuda_bf16.h>
#include <cstdint>

// Hierarchical polarization, persistent-kernel edition.
//   P_0 = pairwise means of Z;  P_{L+1}[G] = mean over pair of (P_L + At_L)
//   out = Z + sum_L At_L[group(s,L)]
// ONE persistent kernel (grid=128, 1 CTA/SM) runs all 14 levels with a
// software grid barrier between levels; warp-level bf16 mma.sync (split
// hi/lo, 3 passes) does the MLP GEMMs; weights staged in smem once per level.

typedef unsigned int u32;

#define NCTA 128

__device__ float g_At[33554432];            // At pyramid, 14 levels, 128 MiB
__device__ float g_UA[8388608];             // P out, even levels
__device__ float g_UB[4194304];             // P out, odd levels
__device__ __nv_bfloat16 g_W1h[10 * 8448];  // [t][h=32][d pad264]  (B for GEMM1)
__device__ __nv_bfloat16 g_W1l[10 * 8448];
__device__ __nv_bfloat16 g_W2h[10 * 10240]; // [t][d=256][h pad40]  (B for GEMM2)
__device__ __nv_bfloat16 g_W2l[10 * 10240];
__device__ float g_b1[320];
__device__ float g_b2[2560];
__device__ unsigned g_barCount = 0;
__device__ unsigned g_barGen   = 0;

__device__ __forceinline__ void grid_sync() {
    __syncthreads();
    if (threadIdx.x == 0) {
        __threadfence();
        unsigned gen = atomicAdd(&g_barGen, 0u);
        if (atomicAdd(&g_barCount, 1u) == (unsigned)(NCTA - 1)) {
            atomicExch(&g_barCount, 0u);
            __threadfence();
            atomicAdd(&g_barGen, 1u);
        } else {
            while (atomicAdd(&g_barGen, 0u) == gen) { __nanosleep(64); }
        }
        __threadfence();
    }
    __syncthreads();
}

__device__ __forceinline__ float gelu_tanh(float x) {
    // jax.nn.gelu approximate=True; tanh(u) = 1 - 2/(exp(2u)+1)
    float u = 0.7978845608028654f * (x + 0.044715f * x * x * x);
    float e = __expf(2.0f * u);
    float t = 1.0f - __fdividef(2.0f, e + 1.0f);
    return 0.5f * x * (1.0f + t);
}
__device__ __forceinline__ long long offF(int l) {
    return (131072LL - (131072LL >> l)) * 256LL;
}
__device__ __forceinline__ void split2(float a, float b, u32& hi, u32& lo) {
    __nv_bfloat16 ha = __float2bfloat16(a), hb = __float2bfloat16(b);
    __nv_bfloat16 la = __float2bfloat16(a - __bfloat162float(ha));
    __nv_bfloat16 lb = __float2bfloat16(b - __bfloat162float(hb));
    hi = (u32)*(unsigned short*)&ha | ((u32)*(unsigned short*)&hb << 16);
    lo = (u32)*(unsigned short*)&la | ((u32)*(unsigned short*)&lb << 16);
}
__device__ __forceinline__ float2 unbf2(u32 v) {
    __nv_bfloat162 t = *(__nv_bfloat162*)&v;
    return make_float2(__bfloat162float(t.x), __bfloat162float(t.y));
}
// D += A(16x16 row) * B(16x8 col), bf16 -> f32
__device__ __forceinline__ void mma16816(float* d, const u32* a, const u32* b) {
    asm volatile("mma.sync.aligned.m16n8k16.row.col.f32.bf16.bf16.f32 "
                 "{%0,%1,%2,%3}, {%4,%5,%6,%7}, {%8,%9}, {%0,%1,%2,%3};"
                 : "+f"(d[0]), "+f"(d[1]), "+f"(d[2]), "+f"(d[3])
                 : "r"(a[0]), "r"(a[1]), "r"(a[2]), "r"(a[3]), "r"(b[0]), "r"(b[1]));
}

// ---------------------------------------------------------------------------
__global__ void setup_weights(const float* __restrict__ W1, const float* __restrict__ W2,
                              const float* __restrict__ b1, const float* __restrict__ b2)
{
    int t = blockIdx.x, tid = threadIdx.x;
    for (int e = tid; e < 8448; e += 256) {
        int h = e / 264, d = e % 264;
        float v = (d < 256) ? W1[t * 8192 + d * 32 + h] : 0.f;
        __nv_bfloat16 hi = __float2bfloat16(v);
        __nv_bfloat16 lo = __float2bfloat16(v - __bfloat162float(hi));
        g_W1h[t * 8448 + e] = hi;
        g_W1l[t * 8448 + e] = lo;
    }
    for (int e = tid; e < 10240; e += 256) {
        int d = e / 40, h = e % 40;
        float v = (h < 32) ? W2[t * 8192 + h * 256 + d] : 0.f;
        __nv_bfloat16 hi = __float2bfloat16(v);
        __nv_bfloat16 lo = __float2bfloat16(v - __bfloat162float(hi));
        g_W2h[t * 10240 + e] = hi;
        g_W2l[t * 10240 + e] = lo;
    }
    if (tid < 32)  g_b1[t * 32 + tid] = b1[t * 32 + tid];
    if (tid < 256) g_b2[t * 256 + tid] = b2[t * 256 + tid];
}

// ---------------------------------------------------------------------------
// Smem layout (bytes). Strides for conflict-free MMA fragment LDS:
//   X stride 264 bf16; H/W2 stride 40 bf16.
// ---------------------------------------------------------------------------
#define XS 264
#define HS 40
#define SM_XHI 0
#define SM_XLO 33792
#define SM_HHI 67584
#define SM_HLO 72704
#define SM_W1H 77824
#define SM_W1L 94720
#define SM_W2H 111616
#define SM_W2L 132096
#define SMEM_TOTAL 152576

// One 64-row tile of one level. All 256 threads participate.
__device__ __forceinline__ void process_tile(
    char* sm, const float4* __restrict__ Z4, const float4* __restrict__ Pin,
    float* __restrict__ Pout, float* __restrict__ AtOut,
    int L, int tt, int nr, long long rbase)
{
    __nv_bfloat16* Xh = (__nv_bfloat16*)(sm + SM_XHI);
    __nv_bfloat16* Xl = (__nv_bfloat16*)(sm + SM_XLO);
    __nv_bfloat16* Hh = (__nv_bfloat16*)(sm + SM_HHI);
    __nv_bfloat16* Hl = (__nv_bfloat16*)(sm + SM_HLO);
    __nv_bfloat16* W1hS = (__nv_bfloat16*)(sm + SM_W1H);
    __nv_bfloat16* W1lS = (__nv_bfloat16*)(sm + SM_W1L);
    __nv_bfloat16* W2hS = (__nv_bfloat16*)(sm + SM_W2H);
    __nv_bfloat16* W2lS = (__nv_bfloat16*)(sm + SM_W2L);

    const int tid  = threadIdx.x;
    const int lane = tid & 31;
    const int w    = tid >> 5;

    // ---- fill X: L0 = pair means of Z rows; L>0 = direct copy of P rows ----
    {
        int r  = tid >> 2;               // 0..63
        int cb = (tid & 3) * 16;
        bool v = r < nr;
        if (L == 0) {
            const float4* p0 = Z4 + (2 * (rbase + r)) * 64;
            const float4* p1 = p0 + 64;
            #pragma unroll 4
            for (int m = 0; m < 16; m++) {
                int c4 = cb + m;
                float4 a = v ? p0[c4] : make_float4(0.f, 0.f, 0.f, 0.f);
                float4 b = v ? p1[c4] : make_float4(0.f, 0.f, 0.f, 0.f);
                float x0 = 0.5f * (a.x + b.x), x1 = 0.5f * (a.y + b.y);
                float x2 = 0.5f * (a.z + b.z), x3 = 0.5f * (a.w + b.w);
                u32 h01, l01, h23, l23;
                split2(x0, x1, h01, l01);
                split2(x2, x3, h23, l23);
                int c = 4 * c4;
                *(u32*)&Xh[r * XS + c]     = h01;
                *(u32*)&Xh[r * XS + c + 2] = h23;
                *(u32*)&Xl[r * XS + c]     = l01;
                *(u32*)&Xl[r * XS + c + 2] = l23;
            }
        } else {
            const float4* p0 = Pin + (rbase + r) * 64;
            #pragma unroll 4
            for (int m = 0; m < 16; m++) {
                int c4 = cb + m;
                float4 a = v ? p0[c4] : make_float4(0.f, 0.f, 0.f, 0.f);
                u32 h01, l01, h23, l23;
                split2(a.x, a.y, h01, l01);
                split2(a.z, a.w, h23, l23);
                int c = 4 * c4;
                *(u32*)&Xh[r * XS + c]     = h01;
                *(u32*)&Xh[r * XS + c + 2] = h23;
                *(u32*)&Xl[r * XS + c]     = l01;
                *(u32*)&Xl[r * XS + c + 2] = l23;
            }
        }
    }
    __syncthreads();

    const int r  = lane >> 2;    // 0..7
    const int cq = lane & 3;     // 0..3

    // ---- GEMM1: warp w -> rows R0..R0+15, cols C1..C1+15 of D1 ----
    const int R0 = (w & 3) * 16;
    const int C1 = (w >> 2) * 16;
    {
        float acc[2][4] = {};
        #pragma unroll 4
        for (int k = 0; k < 16; k++) {
            int kb = k * 16;
            const __nv_bfloat16* xr = Xh + (R0 + r) * XS + kb + 2 * cq;
            const __nv_bfloat16* xs = Xl + (R0 + r) * XS + kb + 2 * cq;
            u32 ah[4] = { *(u32*)xr, *(u32*)(xr + 8 * XS), *(u32*)(xr + 8), *(u32*)(xr + 8 * XS + 8) };
            u32 al[4] = { *(u32*)xs, *(u32*)(xs + 8 * XS), *(u32*)(xs + 8), *(u32*)(xs + 8 * XS + 8) };
            #pragma unroll
            for (int j = 0; j < 2; j++) {
                const __nv_bfloat16* wr = W1hS + (C1 + 8 * j + r) * XS + kb + 2 * cq;
                const __nv_bfloat16* ws = W1lS + (C1 + 8 * j + r) * XS + kb + 2 * cq;
                u32 bh[2] = { *(u32*)wr, *(u32*)(wr + 8) };
                u32 bl[2] = { *(u32*)ws, *(u32*)(ws + 8) };
                mma16816(acc[j], ah, bh);
                mma16816(acc[j], al, bh);
                mma16816(acc[j], ah, bl);
            }
        }
        const float* b1v = g_b1 + tt * 32;
        #pragma unroll
        for (int j = 0; j < 2; j++) {
            int c = C1 + 8 * j + 2 * cq;
            float h0 = gelu_tanh(acc[j][0] + b1v[c]);
            float h1 = gelu_tanh(acc[j][1] + b1v[c + 1]);
            float h2 = gelu_tanh(acc[j][2] + b1v[c]);
            float h3 = gelu_tanh(acc[j][3] + b1v[c + 1]);
            u32 hi, lo;
            split2(h0, h1, hi, lo);
            *(u32*)&Hh[(R0 + r) * HS + c] = hi;
            *(u32*)&Hl[(R0 + r) * HS + c] = lo;
            split2(h2, h3, hi, lo);
            *(u32*)&Hh[(R0 + r + 8) * HS + c] = hi;
            *(u32*)&Hl[(R0 + r + 8) * HS + c] = lo;
        }
    }
    __syncthreads();

    // ---- GEMM2 + epilogue ----
    const int Cb = (w >> 2) * 128;
    const float* b2v = g_b2 + tt * 256;
    for (int ch = 0; ch < 2; ch++) {
        int C2 = Cb + 64 * ch;
        float acc2[8][4] = {};
        #pragma unroll
        for (int k = 0; k < 2; k++) {
            int kb = 16 * k;
            const __nv_bfloat16* hr = Hh + (R0 + r) * HS + kb + 2 * cq;
            const __nv_bfloat16* hs = Hl + (R0 + r) * HS + kb + 2 * cq;
            u32 ah[4] = { *(u32*)hr, *(u32*)(hr + 8 * HS), *(u32*)(hr + 8), *(u32*)(hr + 8 * HS + 8) };
            u32 al[4] = { *(u32*)hs, *(u32*)(hs + 8 * HS), *(u32*)(hs + 8), *(u32*)(hs + 8 * HS + 8) };
            #pragma unroll
            for (int j = 0; j < 8; j++) {
                const __nv_bfloat16* wr = W2hS + (C2 + 8 * j + r) * HS + kb + 2 * cq;
                const __nv_bfloat16* ws = W2lS + (C2 + 8 * j + r) * HS + kb + 2 * cq;
                u32 bh[2] = { *(u32*)wr, *(u32*)(wr + 8) };
                u32 bl[2] = { *(u32*)ws, *(u32*)(ws + 8) };
                mma16816(acc2[j], ah, bh);
                mma16816(acc2[j], al, bh);
                mma16816(acc2[j], ah, bl);
            }
        }
        #pragma unroll
        for (int j = 0; j < 8; j++) {
            int c = C2 + 8 * j + 2 * cq;
            float b20 = b2v[c], b21 = b2v[c + 1];
            float at00 = acc2[j][0] + b20, at01 = acc2[j][1] + b21;
            float at10 = acc2[j][2] + b20, at11 = acc2[j][3] + b21;
            int row0 = R0 + r, row1 = R0 + r + 8;
            float2 xh0 = unbf2(*(u32*)&Xh[row0 * XS + c]);
            float2 xl0 = unbf2(*(u32*)&Xl[row0 * XS + c]);
            float2 xh1 = unbf2(*(u32*)&Xh[row1 * XS + c]);
            float2 xl1 = unbf2(*(u32*)&Xl[row1 * XS + c]);
            float u00 = xh0.x + xl0.x + at00, u01 = xh0.y + xl0.y + at01;
            float u10 = xh1.x + xl1.x + at10, u11 = xh1.y + xl1.y + at11;
            float p00 = __shfl_xor_sync(0xFFFFFFFFu, u00, 4);
            float p01 = __shfl_xor_sync(0xFFFFFFFFu, u01, 4);
            float p10 = __shfl_xor_sync(0xFFFFFFFFu, u10, 4);
            float p11 = __shfl_xor_sync(0xFFFFFFFFu, u11, 4);
            if (row0 < nr) {
                *(float2*)&AtOut[(rbase + row0) * 256 + c] = make_float2(at00, at01);
                if (row1 < nr)
                    *(float2*)&AtOut[(rbase + row1) * 256 + c] = make_float2(at10, at11);
                if (!(r & 1)) {
                    *(float2*)&Pout[((rbase + row0) >> 1) * 256 + c] =
                        make_float2(0.5f * (u00 + p00), 0.5f * (u01 + p01));
                    if (row1 < nr)
                        *(float2*)&Pout[((rbase + row1) >> 1) * 256 + c] =
                            make_float2(0.5f * (u10 + p10), 0.5f * (u11 + p11));
                }
            }
        }
    }
}

// ---------------------------------------------------------------------------
// Persistent kernel: all 14 levels, grid barrier between levels.
// ---------------------------------------------------------------------------
__global__ void __launch_bounds__(256, 1) persist_kernel(const float4* __restrict__ Z4)
{
    extern __shared__ char sm[];
    const int tid = threadIdx.x;
    int prevTT = -1;

    for (int L = 0; L < 14; L++) {
        int rowsP  = 65536 >> L;
        int ntiles = (rowsP + 63) >> 6;
        int tt     = (L < 10) ? L : 9;
        const float4* Pin = (L == 0) ? Z4
                          : ((L & 1) ? (const float4*)g_UA : (const float4*)g_UB);
        float* Pout  = (L & 1) ? g_UB : g_UA;
        float* AtOut = g_At + offF(L);

        if (tt != prevTT) {
            // stage this level's weight images into smem (once per level)
            u32* d1h = (u32*)(sm + SM_W1H); const u32* s1h = (const u32*)(g_W1h + tt * 8448);
            u32* d1l = (u32*)(sm + SM_W1L); const u32* s1l = (const u32*)(g_W1l + tt * 8448);
            for (int i = tid; i < 4224; i += 256) { d1h[i] = s1h[i]; d1l[i] = s1l[i]; }
            u32* d2h = (u32*)(sm + SM_W2H); const u32* s2h = (const u32*)(g_W2h + tt * 10240);
            u32* d2l = (u32*)(sm + SM_W2L); const u32* s2l = (const u32*)(g_W2l + tt * 10240);
            for (int i = tid; i < 5120; i += 256) { d2h[i] = s2h[i]; d2l[i] = s2l[i]; }
            prevTT = tt;
        }
        __syncthreads();

        for (int tile = blockIdx.x; tile < ntiles; tile += NCTA) {
            long long rbase = (long long)tile * 64;
            int nr = rowsP - tile * 64; if (nr > 64) nr = 64;
            process_tile(sm, Z4, Pin, Pout, AtOut, L, tt, nr, rbase);
            __syncthreads();
        }
        grid_sync();
    }
}

// ---------------------------------------------------------------------------
// out = Z + sum over 14 levels of At[level][b, s>>(L+1), d]
// ---------------------------------------------------------------------------
__global__ void __launch_bounds__(256) final_kernel(
    const float4* __restrict__ Z4, float4* __restrict__ out4)
{
    int i   = blockIdx.x * 256 + threadIdx.x;
    int d4  = i & 63;
    int row = i >> 6;
    int b   = row >> 14;
    int s   = row & 16383;

    const float4* At4 = (const float4*)g_At;
    float4 acc = Z4[i];
    long long off4 = 0;
    int ng = 8192;
    #pragma unroll
    for (int L = 0; L < 14; L++) {
        int g = s >> (L + 1);
        float4 a = At4[off4 + (long long)(b * ng + g) * 64 + d4];
        acc.x += a.x; acc.y += a.y; acc.z += a.z; acc.w += a.w;
        off4 += 512LL * ng;
        ng >>= 1;
    }
    out4[i] = acc;
}

extern "C" void kernel_launch(void* const* d_in, const int* in_sizes, int n_in,
                              void* d_out, int out_size)
{
    const float* Z  = (const float*)d_in[0];
    const float* W1 = (const float*)d_in[1];
    const float* b1 = (const float*)d_in[2];
    const float* W2 = (const float*)d_in[3];
    const float* b2 = (const float*)d_in[4];

    cudaFuncSetAttribute(persist_kernel,
                         cudaFuncAttributeMaxDynamicSharedMemorySize, SMEM_TOTAL);

    setup_weights<<<10, 256>>>(W1, W2, b1, b2);
    persist_kernel<<<NCTA, 256, SMEM_TOTAL>>>((const float4*)Z);
    final_kernel<<<32768, 256>>>((const float4*)Z, (float4*)d_out);
}